// round 6
// baseline (speedup 1.0000x reference)
#include <cuda_runtime.h>
#include <cuda_bf16.h>
#include <cuda_fp16.h>
#include <cstdint>

// Problem constants (fixed by the dataset)
#define NN   100000      // nodes
#define EE   1600000     // edges
#define CAP  128         // adjacency bucket capacity per node
#define NSM  152         // GB300 SM count

// ---------------- scratch (device globals; no allocation allowed) ----------
__device__ __half         g_h0[(size_t)NN * 128];   // x @ W1 (fp16)
__device__ __nv_bfloat16  g_h1hi[(size_t)NN * 128]; // relu(agg h0), bf16 hi
__device__ __nv_bfloat16  g_h1lo[(size_t)NN * 128]; // bf16 lo plane
__device__ __half         g_h2[(size_t)NN * 64];    // h1 @ W2 (fp16)
__device__ __nv_bfloat16  g_xhi[(size_t)NN * 128];  // x bf16 hi
__device__ __nv_bfloat16  g_xlo[(size_t)NN * 128];  // x bf16 lo
__device__ int            g_deg[NN];
__device__ int            g_adj[(size_t)NN * CAP];
__device__ __nv_bfloat16  g_w1hi[128 * 128], g_w1lo[128 * 128];
__device__ __nv_bfloat16  g_w2hi[64 * 128],  g_w2lo[64 * 128];

#define ROWB 272   // smem row pitch: 128 bf16 (256B) + 16B pad, ldmatrix conflict-free

// ---------------- prep: clear degrees + weight hi/lo transpose --------------
__global__ void k_prep_clear(const float* __restrict__ W1, const float* __restrict__ W2,
                             __nv_bfloat16* __restrict__ w1hi, __nv_bfloat16* __restrict__ w1lo,
                             __nv_bfloat16* __restrict__ w2hi, __nv_bfloat16* __restrict__ w2lo) {
    int i = blockIdx.x * blockDim.x + threadIdx.x;
    if (i < NN) g_deg[i] = 0;
    if (i < 128 * 128) {
        int k = i / 128, n = i % 128;
        float w = W1[i];
        __nv_bfloat16 h = __float2bfloat16_rn(w);
        w1hi[n * 128 + k] = h;
        w1lo[n * 128 + k] = __float2bfloat16_rn(w - __bfloat162float(h));
    } else if (i < 128 * 128 + 128 * 64) {
        int j = i - 128 * 128;
        int k = j / 64, n = j % 64;
        float w = W2[j];
        __nv_bfloat16 h = __float2bfloat16_rn(w);
        w2hi[n * 128 + k] = h;
        w2lo[n * 128 + k] = __float2bfloat16_rn(w - __bfloat162float(h));
    }
}

// ---------------- fused: x -> bf16 hi/lo split  +  adjacency build ----------
__global__ void k_conv_build(const float* __restrict__ x,
                             const int* __restrict__ erow, const int* __restrict__ ecol,
                             __nv_bfloat16* __restrict__ xhi, __nv_bfloat16* __restrict__ xlo) {
    int i = blockIdx.x * blockDim.x + threadIdx.x;

    // adjacency: first EE/4 threads, 4 edges each (4 atomic chains in flight)
    if (i < EE / 4) {
        int4 r = *reinterpret_cast<const int4*>(erow + i * 4);
        int4 c = *reinterpret_cast<const int4*>(ecol + i * 4);
        int p0 = atomicAdd(&g_deg[r.x], 1);
        int p1 = atomicAdd(&g_deg[r.y], 1);
        int p2 = atomicAdd(&g_deg[r.z], 1);
        int p3 = atomicAdd(&g_deg[r.w], 1);
        if (p0 < CAP) g_adj[(size_t)r.x * CAP + p0] = c.x;
        if (p1 < CAP) g_adj[(size_t)r.y * CAP + p1] = c.y;
        if (p2 < CAP) g_adj[(size_t)r.z * CAP + p2] = c.z;
        if (p3 < CAP) g_adj[(size_t)r.w * CAP + p3] = c.w;
    }

    // x conversion: chunk i = 4 floats (flat layout matches [node][dim])
    if (i < NN * 32) {
        float4 v = reinterpret_cast<const float4*>(x)[i];
        __nv_bfloat162 h01 = __float22bfloat162_rn(make_float2(v.x, v.y));
        __nv_bfloat162 h23 = __float22bfloat162_rn(make_float2(v.z, v.w));
        float2 f01 = __bfloat1622float2(h01);
        float2 f23 = __bfloat1622float2(h23);
        __nv_bfloat162 l01 = __float22bfloat162_rn(make_float2(v.x - f01.x, v.y - f01.y));
        __nv_bfloat162 l23 = __float22bfloat162_rn(make_float2(v.z - f23.x, v.w - f23.y));
        uint2 hh = make_uint2(*reinterpret_cast<uint32_t*>(&h01),
                              *reinterpret_cast<uint32_t*>(&h23));
        uint2 ll = make_uint2(*reinterpret_cast<uint32_t*>(&l01),
                              *reinterpret_cast<uint32_t*>(&l23));
        *reinterpret_cast<uint2*>(xhi + (size_t)i * 4) = hh;
        *reinterpret_cast<uint2*>(xlo + (size_t)i * 4) = ll;
    }
}

// ---------------- mma / ldmatrix helpers -------------------------------------
#define LDMX4(r0, r1, r2, r3, addr) \
    asm volatile("ldmatrix.sync.aligned.m8n8.x4.shared.b16 {%0,%1,%2,%3}, [%4];" \
                 : "=r"(r0), "=r"(r1), "=r"(r2), "=r"(r3) : "r"(addr))
#define LDMX2(r0, r1, addr) \
    asm volatile("ldmatrix.sync.aligned.m8n8.x2.shared.b16 {%0,%1}, [%2];" \
                 : "=r"(r0), "=r"(r1) : "r"(addr))
#define MMA_BF16(acc, a, b0, b1) \
    asm volatile("mma.sync.aligned.m16n8k16.row.col.f32.bf16.bf16.f32 " \
                 "{%0,%1,%2,%3}, {%4,%5,%6,%7}, {%8,%9}, {%0,%1,%2,%3};" \
                 : "+f"(acc[0]), "+f"(acc[1]), "+f"(acc[2]), "+f"(acc[3]) \
                 : "r"(a[0]), "r"(a[1]), "r"(a[2]), "r"(a[3]), "r"(b0), "r"(b1))
#define CP_ASYNC16(dst, src, sz) \
    asm volatile("cp.async.cg.shared.global [%0], [%1], 16, %2;" \
                 :: "r"(dst), "l"(src), "r"(sz))

// ---------------- persistent pipelined bf16 GEMM -----------------------------
// C[nrows, NCOL](fp16) = A[nrows,128] @ W[128,NCOL], A & B pre-split bf16 hi/lo.
// 3-pass Dekker: Ah*Bh + Ah*Bl + Al*Bh, fp32 acc.
// 512 threads = 16 warps (4M x 4N); A tile 128 rows, double-buffered cp.async.
template <int NCOL>
__global__ __launch_bounds__(512, 1)
void k_gemm(const __nv_bfloat16* __restrict__ Ahi, const __nv_bfloat16* __restrict__ Alo,
            const __nv_bfloat16* __restrict__ Bhi, const __nv_bfloat16* __restrict__ Blo,
            __half* __restrict__ C, int nrows) {
    constexpr int B_BYTES = NCOL * ROWB;
    constexpr int PLANE = 128 * ROWB;     // one A plane (34816 B)
    constexpr int PAIR = 2 * PLANE;       // one A buffer (hi+lo)
    constexpr int WN = NCOL / 4;
    constexpr int NT = WN / 8;

    extern __shared__ char smem[];
    char* sBhi = smem;
    char* sBlo = smem + B_BYTES;
    char* sA   = smem + 2 * B_BYTES;
    const uint32_t sA_u = (uint32_t)__cvta_generic_to_shared(sA);

    const int tid = threadIdx.x;
    const int lane = tid & 31;
    const int wid = tid >> 5;
    const int g = lane >> 2;
    const int tg = lane & 3;
    const int mbase = (wid & 3) * 32;
    const int nbase = (wid >> 2) * WN;

    // ---- stage B hi/lo once ---------------------------------------------------
    for (int i = tid; i < NCOL * 16; i += 512) {
        int n = i >> 4, q = i & 15;
        *reinterpret_cast<uint4*>(sBhi + n * ROWB + q * 16) =
            reinterpret_cast<const uint4*>(Bhi + n * 128)[q];
        *reinterpret_cast<uint4*>(sBlo + n * ROWB + q * 16) =
            reinterpret_cast<const uint4*>(Blo + n * 128)[q];
    }

    // ---- ldmatrix base addresses ----------------------------------------------
    const int rlm = lane & 7;
    const int qa = lane >> 3;
    uint32_t aA[2];  // hi-plane offset within buffer; lo = +PLANE
#pragma unroll
    for (int mt = 0; mt < 2; mt++) {
        int row = mbase + mt * 16 + (qa & 1) * 8 + rlm;
        aA[mt] = sA_u + row * ROWB + (qa >> 1) * 16;
    }
    const int lb = lane & 15;
    uint32_t aBhi[NT], aBlo[NT];
#pragma unroll
    for (int nt = 0; nt < NT; nt++) {
        int row = nbase + nt * 8 + (lb & 7);
        int col = ((lb >> 3) & 1) * 16;
        aBhi[nt] = (uint32_t)__cvta_generic_to_shared(sBhi) + row * ROWB + col;
        aBlo[nt] = (uint32_t)__cvta_generic_to_shared(sBlo) + row * ROWB + col;
    }

    const int ntiles = (nrows + 127) >> 7;

    // prefetch one 128-row A tile (hi+lo) into buffer b
    auto prefetch = [&](int t, int b) {
        const int r0 = t * 128;
#pragma unroll
        for (int it = 0; it < 8; it++) {
            int idx = tid + it * 512;           // 4096 chunks: 2 planes x 128 rows x 16
            int plane = idx >> 11;
            int rr = (idx & 2047) >> 4;
            int cc = idx & 15;
            int gr = r0 + rr;
            unsigned sz = (gr < nrows) ? 16u : 0u;
            int grc = gr < nrows ? gr : (nrows - 1);
            const char* src =
                reinterpret_cast<const char*>(plane ? Alo : Ahi) + (size_t)grc * 256 + cc * 16;
            uint32_t dst = sA_u + b * PAIR + plane * PLANE + rr * ROWB + cc * 16;
            CP_ASYNC16(dst, src, sz);
        }
        asm volatile("cp.async.commit_group;");
    };

    int buf = 0;
    prefetch(blockIdx.x, 0);  // every CTA has work: ntiles(782) > grid(152)

    for (int t = blockIdx.x; t < ntiles; t += gridDim.x) {
        const int tn = t + gridDim.x;
        if (tn < ntiles) {
            prefetch(tn, buf ^ 1);
            asm volatile("cp.async.wait_group 1;");
        } else {
            asm volatile("cp.async.wait_group 0;");
        }
        __syncthreads();  // A[buf] ready for all; B staged (first iter)

        const uint32_t bo = buf * PAIR;
        float acc[2][NT][4];
#pragma unroll
        for (int mt = 0; mt < 2; mt++)
#pragma unroll
            for (int nt = 0; nt < NT; nt++)
#pragma unroll
                for (int j = 0; j < 4; j++) acc[mt][nt][j] = 0.0f;

#pragma unroll
        for (int ks = 0; ks < 8; ks++) {
            const uint32_t ko = ks * 32;
            uint32_t ah[2][4], al[2][4];
#pragma unroll
            for (int mt = 0; mt < 2; mt++) {
                LDMX4(ah[mt][0], ah[mt][1], ah[mt][2], ah[mt][3], aA[mt] + bo + ko);
                LDMX4(al[mt][0], al[mt][1], al[mt][2], al[mt][3], aA[mt] + bo + PLANE + ko);
            }
#pragma unroll
            for (int nt = 0; nt < NT; nt++) {
                uint32_t bh0, bh1, bl0, bl1;
                LDMX2(bh0, bh1, aBhi[nt] + ko);
                LDMX2(bl0, bl1, aBlo[nt] + ko);
#pragma unroll
                for (int mt = 0; mt < 2; mt++) {
                    MMA_BF16(acc[mt][nt], ah[mt], bh0, bh1);
                    MMA_BF16(acc[mt][nt], ah[mt], bl0, bl1);
                    MMA_BF16(acc[mt][nt], al[mt], bh0, bh1);
                }
            }
        }

        // epilogue: fp32 acc -> fp16
        const int r0 = t * 128;
#pragma unroll
        for (int mt = 0; mt < 2; mt++) {
#pragma unroll
            for (int nt = 0; nt < NT; nt++) {
                int r1 = r0 + mbase + mt * 16 + g;
                int r2 = r1 + 8;
                int cc = nbase + nt * 8 + tg * 2;
                if (r1 < nrows)
                    *reinterpret_cast<__half2*>(C + (size_t)r1 * NCOL + cc) =
                        __floats2half2_rn(acc[mt][nt][0], acc[mt][nt][1]);
                if (r2 < nrows)
                    *reinterpret_cast<__half2*>(C + (size_t)r2 * NCOL + cc) =
                        __floats2half2_rn(acc[mt][nt][2], acc[mt][nt][3]);
            }
        }

        __syncthreads();  // all reads of A[buf] done before it is re-prefetched
        buf ^= 1;
    }
}

// ---------------- agg1: mean + relu, fp16 in -> bf16 hi/lo out ---------------
__global__ void k_agg1(const __half* __restrict__ src,
                       __nv_bfloat16* __restrict__ dhi, __nv_bfloat16* __restrict__ dlo) {
    const int gw = (blockIdx.x * blockDim.x + threadIdx.x) >> 5;
    if (gw >= NN) return;
    const int lane = threadIdx.x & 31;

    const int d = g_deg[gw];
    const int cnt = d < CAP ? d : CAP;
    const int* __restrict__ adj = g_adj + (size_t)gw * CAP;

    float acc[4] = {0.f, 0.f, 0.f, 0.f};
#pragma unroll 4
    for (int t = 0; t < cnt; t++) {
        int j = __ldg(&adj[t]);
        uint2 v = *reinterpret_cast<const uint2*>(src + (size_t)j * 128 + lane * 4);
        float2 f0 = __half22float2(*reinterpret_cast<__half2*>(&v.x));
        float2 f1 = __half22float2(*reinterpret_cast<__half2*>(&v.y));
        acc[0] += f0.x; acc[1] += f0.y; acc[2] += f1.x; acc[3] += f1.y;
    }

    const float inv = 1.0f / (float)d;
    float o0 = fmaxf(acc[0] * inv, 0.f), o1 = fmaxf(acc[1] * inv, 0.f);
    float o2 = fmaxf(acc[2] * inv, 0.f), o3 = fmaxf(acc[3] * inv, 0.f);

    __nv_bfloat162 h01 = __float22bfloat162_rn(make_float2(o0, o1));
    __nv_bfloat162 h23 = __float22bfloat162_rn(make_float2(o2, o3));
    float2 f01 = __bfloat1622float2(h01);
    float2 f23 = __bfloat1622float2(h23);
    __nv_bfloat162 l01 = __float22bfloat162_rn(make_float2(o0 - f01.x, o1 - f01.y));
    __nv_bfloat162 l23 = __float22bfloat162_rn(make_float2(o2 - f23.x, o3 - f23.y));

    size_t off = (size_t)gw * 128 + lane * 4;
    *reinterpret_cast<uint2*>(dhi + off) = make_uint2(
        *reinterpret_cast<uint32_t*>(&h01), *reinterpret_cast<uint32_t*>(&h23));
    *reinterpret_cast<uint2*>(dlo + off) = make_uint2(
        *reinterpret_cast<uint32_t*>(&l01), *reinterpret_cast<uint32_t*>(&l23));
}

// ---------------- agg2: mean, fp16 in -> fp32 out -----------------------------
__global__ void k_agg2(const __half* __restrict__ src, float* __restrict__ dst) {
    const int gw = (blockIdx.x * blockDim.x + threadIdx.x) >> 5;
    if (gw >= NN) return;
    const int lane = threadIdx.x & 31;

    const int d = g_deg[gw];
    const int cnt = d < CAP ? d : CAP;
    const int* __restrict__ adj = g_adj + (size_t)gw * CAP;

    float acc0 = 0.f, acc1 = 0.f;
#pragma unroll 4
    for (int t = 0; t < cnt; t++) {
        int j = __ldg(&adj[t]);
        uint32_t v = *reinterpret_cast<const uint32_t*>(src + (size_t)j * 64 + lane * 2);
        float2 f = __half22float2(*reinterpret_cast<__half2*>(&v));
        acc0 += f.x; acc1 += f.y;
    }
    const float inv = 1.0f / (float)d;
    *reinterpret_cast<float2*>(dst + (size_t)gw * 64 + lane * 2) =
        make_float2(acc0 * inv, acc1 * inv);
}

// ---------------- launch --------------------------------------------------------
extern "C" void kernel_launch(void* const* d_in, const int* in_sizes, int n_in,
                              void* d_out, int out_size) {
    const float* x    = (const float*)d_in[0];
    const float* W1   = (const float*)d_in[1];
    const float* W2   = (const float*)d_in[2];
    const int*   erow = (const int*)d_in[3];
    const int*   ecol = (const int*)d_in[4];
    float* out = (float*)d_out;

    __half *h0, *h2;
    __nv_bfloat16 *h1hi, *h1lo, *xhi, *xlo, *w1hi, *w1lo, *w2hi, *w2lo;
    cudaGetSymbolAddress((void**)&h0,   g_h0);
    cudaGetSymbolAddress((void**)&h1hi, g_h1hi);
    cudaGetSymbolAddress((void**)&h1lo, g_h1lo);
    cudaGetSymbolAddress((void**)&h2,   g_h2);
    cudaGetSymbolAddress((void**)&xhi,  g_xhi);
    cudaGetSymbolAddress((void**)&xlo,  g_xlo);
    cudaGetSymbolAddress((void**)&w1hi, g_w1hi);
    cudaGetSymbolAddress((void**)&w1lo, g_w1lo);
    cudaGetSymbolAddress((void**)&w2hi, g_w2hi);
    cudaGetSymbolAddress((void**)&w2lo, g_w2lo);

    const int SMEM1 = 2 * 128 * ROWB + 2 * 2 * 128 * ROWB;  // 208896
    const int SMEM2 = 2 * 64 * ROWB + 2 * 2 * 128 * ROWB;   // 174080
    cudaFuncSetAttribute(k_gemm<128>, cudaFuncAttributeMaxDynamicSharedMemorySize, SMEM1);
    cudaFuncSetAttribute(k_gemm<64>,  cudaFuncAttributeMaxDynamicSharedMemorySize, SMEM2);

    k_prep_clear<<<(NN + 255) / 256, 256>>>(W1, W2, w1hi, w1lo, w2hi, w2lo);      // 1
    k_conv_build<<<(NN * 32 + 255) / 256, 256>>>(x, erow, ecol, xhi, xlo);        // 2
    k_gemm<128><<<NSM, 512, SMEM1>>>(xhi, xlo, w1hi, w1lo, h0, NN);               // 3
    k_agg1<<<(NN * 32 + 255) / 256, 256>>>(h0, h1hi, h1lo);                       // 4 (slot 4)
    k_gemm<64><<<NSM, 512, SMEM2>>>(h1hi, h1lo, w2hi, w2lo, h2, NN);              // 5
    k_agg2<<<(NN * 32 + 255) / 256, 256>>>(h2, out);                              // 6
}

// round 7
// speedup vs baseline: 1.0206x; 1.0206x over previous
#include <cuda_runtime.h>
#include <cuda_bf16.h>
#include <cuda_fp16.h>
#include <cstdint>

// Problem constants (fixed by the dataset)
#define NN   100000      // nodes
#define EE   1600000     // edges
#define CAP  128         // adjacency bucket capacity per node
#define NSM  152         // GB300 SM count

// ---------------- scratch (device globals; no allocation allowed) ----------
__device__ __half         g_h0[(size_t)NN * 128];   // x @ W1 (fp16)
__device__ __nv_bfloat16  g_h1hi[(size_t)NN * 128]; // relu(agg h0), bf16 hi
__device__ __nv_bfloat16  g_h1lo[(size_t)NN * 128]; // bf16 lo plane
__device__ __half         g_h2[(size_t)NN * 64];    // h1 @ W2 (fp16)
__device__ int            g_deg[NN];
__device__ int            g_adj[(size_t)NN * CAP];
__device__ __nv_bfloat16  g_w1hi[128 * 128], g_w1lo[128 * 128];
__device__ __nv_bfloat16  g_w2hi[64 * 128],  g_w2lo[64 * 128];

#define ROWB 272   // smem row pitch: 128 bf16 (256B) + 16B pad, ldmatrix conflict-free

// ---------------- prep 1: clear degrees + W1 hi/lo transpose ----------------
__global__ void k_prep_w1(const float* __restrict__ W1,
                          __nv_bfloat16* __restrict__ w1hi, __nv_bfloat16* __restrict__ w1lo) {
    int i = blockIdx.x * blockDim.x + threadIdx.x;
    if (i < NN) g_deg[i] = 0;
    if (i < 128 * 128) {
        int k = i / 128, n = i % 128;
        float w = W1[i];
        __nv_bfloat16 h = __float2bfloat16_rn(w);
        w1hi[n * 128 + k] = h;
        w1lo[n * 128 + k] = __float2bfloat16_rn(w - __bfloat162float(h));
    }
}

// ---------------- prep 2: W2 hi/lo transpose --------------------------------
__global__ void k_prep_w2(const float* __restrict__ W2,
                          __nv_bfloat16* __restrict__ w2hi, __nv_bfloat16* __restrict__ w2lo) {
    int i = blockIdx.x * blockDim.x + threadIdx.x;
    if (i < 128 * 64) {
        int k = i / 64, n = i % 64;
        float w = W2[i];
        __nv_bfloat16 h = __float2bfloat16_rn(w);
        w2hi[n * 128 + k] = h;
        w2lo[n * 128 + k] = __float2bfloat16_rn(w - __bfloat162float(h));
    }
}

// ---------------- adjacency build: 4 edges/thread ---------------------------
__global__ void k_build_adj(const int* __restrict__ erow,
                            const int* __restrict__ ecol) {
    int e0 = (blockIdx.x * blockDim.x + threadIdx.x) * 4;
    if (e0 >= EE) return;
    int4 r = *reinterpret_cast<const int4*>(erow + e0);
    int4 c = *reinterpret_cast<const int4*>(ecol + e0);
    int p0 = atomicAdd(&g_deg[r.x], 1);
    int p1 = atomicAdd(&g_deg[r.y], 1);
    int p2 = atomicAdd(&g_deg[r.z], 1);
    int p3 = atomicAdd(&g_deg[r.w], 1);
    if (p0 < CAP) g_adj[(size_t)r.x * CAP + p0] = c.x;
    if (p1 < CAP) g_adj[(size_t)r.y * CAP + p1] = c.y;
    if (p2 < CAP) g_adj[(size_t)r.z * CAP + p2] = c.z;
    if (p3 < CAP) g_adj[(size_t)r.w * CAP + p3] = c.w;
}

// ---------------- mma / ldmatrix helpers -------------------------------------
#define LDMX4(r0, r1, r2, r3, addr) \
    asm volatile("ldmatrix.sync.aligned.m8n8.x4.shared.b16 {%0,%1,%2,%3}, [%4];" \
                 : "=r"(r0), "=r"(r1), "=r"(r2), "=r"(r3) : "r"(addr))
#define LDMX2(r0, r1, addr) \
    asm volatile("ldmatrix.sync.aligned.m8n8.x2.shared.b16 {%0,%1}, [%2];" \
                 : "=r"(r0), "=r"(r1) : "r"(addr))
#define MMA_BF16(acc, a, b0, b1) \
    asm volatile("mma.sync.aligned.m16n8k16.row.col.f32.bf16.bf16.f32 " \
                 "{%0,%1,%2,%3}, {%4,%5,%6,%7}, {%8,%9}, {%0,%1,%2,%3};" \
                 : "+f"(acc[0]), "+f"(acc[1]), "+f"(acc[2]), "+f"(acc[3]) \
                 : "r"(a[0]), "r"(a[1]), "r"(a[2]), "r"(a[3]), "r"(b0), "r"(b1))

// ---------------- GEMM1: fp32 A, in-kernel bf16 hi/lo split ------------------
// C[nrows,128](fp16) = A[nrows,128](fp32) @ W1. 8 warps = 2M x 4N; 64-row tiles.
__global__ __launch_bounds__(256, 2)
void k_gemm_conv(const float* __restrict__ A,
                 const __nv_bfloat16* __restrict__ Bhi, const __nv_bfloat16* __restrict__ Blo,
                 __half* __restrict__ C, int nrows) {
    constexpr int NCOL = 128;
    constexpr int WN = 32, NT = 4;
    constexpr int B_BYTES = NCOL * ROWB;
    constexpr int A_BYTES = 64 * ROWB;

    extern __shared__ char smem[];
    char* sBhi = smem;
    char* sBlo = smem + B_BYTES;
    char* sAhi = sBlo + B_BYTES;
    char* sAlo = sAhi + A_BYTES;

    const int tid = threadIdx.x;
    const int lane = tid & 31;
    const int wid = tid >> 5;
    const int g = lane >> 2;
    const int tg = lane & 3;
    const int mbase = (wid & 1) * 32;
    const int nbase = (wid >> 1) * WN;

    // stage B hi/lo once
    for (int i = tid; i < NCOL * 16; i += 256) {
        int n = i >> 4, q = i & 15;
        *reinterpret_cast<uint4*>(sBhi + n * ROWB + q * 16) =
            reinterpret_cast<const uint4*>(Bhi + n * 128)[q];
        *reinterpret_cast<uint4*>(sBlo + n * ROWB + q * 16) =
            reinterpret_cast<const uint4*>(Blo + n * 128)[q];
    }

    // ldmatrix base addresses
    const int rlm = lane & 7;
    const int qa = lane >> 3;
    uint32_t aAhi[2], aAlo[2];
#pragma unroll
    for (int mt = 0; mt < 2; mt++) {
        int row = mbase + mt * 16 + (qa & 1) * 8 + rlm;
        int col = (qa >> 1) * 16;
        aAhi[mt] = (uint32_t)__cvta_generic_to_shared(sAhi) + row * ROWB + col;
        aAlo[mt] = (uint32_t)__cvta_generic_to_shared(sAlo) + row * ROWB + col;
    }
    const int lb = lane & 15;
    uint32_t aBhi[NT], aBlo[NT];
#pragma unroll
    for (int nt = 0; nt < NT; nt++) {
        int row = nbase + nt * 8 + (lb & 7);
        int col = ((lb >> 3) & 1) * 16;
        aBhi[nt] = (uint32_t)__cvta_generic_to_shared(sBhi) + row * ROWB + col;
        aBlo[nt] = (uint32_t)__cvta_generic_to_shared(sBlo) + row * ROWB + col;
    }

    const int ntiles = (nrows + 63) / 64;
    for (int t = blockIdx.x; t < ntiles; t += gridDim.x) {
        const int r0 = t * 64;
        __syncthreads();

        // stage A tile: fp32 -> bf16 hi/lo
#pragma unroll
        for (int it = 0; it < 8; it++) {
            int i = tid + it * 256;
            int m = i >> 5;
            int q = i & 31;
            float4 v = make_float4(0.f, 0.f, 0.f, 0.f);
            int gr = r0 + m;
            if (gr < nrows)
                v = *reinterpret_cast<const float4*>(A + (size_t)gr * 128 + q * 4);
            __nv_bfloat162 h01 = __float22bfloat162_rn(make_float2(v.x, v.y));
            __nv_bfloat162 h23 = __float22bfloat162_rn(make_float2(v.z, v.w));
            float2 f01 = __bfloat1622float2(h01);
            float2 f23 = __bfloat1622float2(h23);
            __nv_bfloat162 l01 = __float22bfloat162_rn(make_float2(v.x - f01.x, v.y - f01.y));
            __nv_bfloat162 l23 = __float22bfloat162_rn(make_float2(v.z - f23.x, v.w - f23.y));
            uint2 hh = make_uint2(*reinterpret_cast<uint32_t*>(&h01),
                                  *reinterpret_cast<uint32_t*>(&h23));
            uint2 ll = make_uint2(*reinterpret_cast<uint32_t*>(&l01),
                                  *reinterpret_cast<uint32_t*>(&l23));
            *reinterpret_cast<uint2*>(sAhi + m * ROWB + q * 8) = hh;
            *reinterpret_cast<uint2*>(sAlo + m * ROWB + q * 8) = ll;
        }
        __syncthreads();

        float acc[2][NT][4];
#pragma unroll
        for (int mt = 0; mt < 2; mt++)
#pragma unroll
            for (int nt = 0; nt < NT; nt++)
#pragma unroll
                for (int j = 0; j < 4; j++) acc[mt][nt][j] = 0.0f;

#pragma unroll
        for (int ks = 0; ks < 8; ks++) {
            const uint32_t ko = ks * 32;
            uint32_t ah[2][4], al[2][4];
#pragma unroll
            for (int mt = 0; mt < 2; mt++) {
                LDMX4(ah[mt][0], ah[mt][1], ah[mt][2], ah[mt][3], aAhi[mt] + ko);
                LDMX4(al[mt][0], al[mt][1], al[mt][2], al[mt][3], aAlo[mt] + ko);
            }
#pragma unroll
            for (int nt = 0; nt < NT; nt++) {
                uint32_t bh0, bh1, bl0, bl1;
                LDMX2(bh0, bh1, aBhi[nt] + ko);
                LDMX2(bl0, bl1, aBlo[nt] + ko);
#pragma unroll
                for (int mt = 0; mt < 2; mt++) {
                    MMA_BF16(acc[mt][nt], ah[mt], bh0, bh1);
                    MMA_BF16(acc[mt][nt], ah[mt], bl0, bl1);
                    MMA_BF16(acc[mt][nt], al[mt], bh0, bh1);
                }
            }
        }

        // epilogue: fp16 out
#pragma unroll
        for (int mt = 0; mt < 2; mt++) {
#pragma unroll
            for (int nt = 0; nt < NT; nt++) {
                int r1 = r0 + mbase + mt * 16 + g;
                int r2 = r1 + 8;
                int cc = nbase + nt * 8 + tg * 2;
                if (r1 < nrows)
                    *reinterpret_cast<__half2*>(C + (size_t)r1 * NCOL + cc) =
                        __floats2half2_rn(acc[mt][nt][0], acc[mt][nt][1]);
                if (r2 < nrows)
                    *reinterpret_cast<__half2*>(C + (size_t)r2 * NCOL + cc) =
                        __floats2half2_rn(acc[mt][nt][2], acc[mt][nt][3]);
            }
        }
    }
}

// ---------------- GEMM2: pre-split bf16 A planes -----------------------------
// C[nrows,64](fp16) = A[nrows,128](bf16 hi/lo) @ W2. 8 warps = 2M x 4N.
__global__ __launch_bounds__(256, 3)
void k_gemm_pre(const __nv_bfloat16* __restrict__ Ahi, const __nv_bfloat16* __restrict__ Alo,
                const __nv_bfloat16* __restrict__ Bhi, const __nv_bfloat16* __restrict__ Blo,
                __half* __restrict__ C, int nrows) {
    constexpr int NCOL = 64;
    constexpr int WN = 16, NT = 2;
    constexpr int B_BYTES = NCOL * ROWB;
    constexpr int A_BYTES = 64 * ROWB;

    extern __shared__ char smem[];
    char* sBhi = smem;
    char* sBlo = smem + B_BYTES;
    char* sAhi = sBlo + B_BYTES;
    char* sAlo = sAhi + A_BYTES;

    const int tid = threadIdx.x;
    const int lane = tid & 31;
    const int wid = tid >> 5;
    const int g = lane >> 2;
    const int tg = lane & 3;
    const int mbase = (wid & 1) * 32;
    const int nbase = (wid >> 1) * WN;

    // stage B hi/lo once
    for (int i = tid; i < NCOL * 16; i += 256) {
        int n = i >> 4, q = i & 15;
        *reinterpret_cast<uint4*>(sBhi + n * ROWB + q * 16) =
            reinterpret_cast<const uint4*>(Bhi + n * 128)[q];
        *reinterpret_cast<uint4*>(sBlo + n * ROWB + q * 16) =
            reinterpret_cast<const uint4*>(Blo + n * 128)[q];
    }

    const int rlm = lane & 7;
    const int qa = lane >> 3;
    uint32_t aAhi[2], aAlo[2];
#pragma unroll
    for (int mt = 0; mt < 2; mt++) {
        int row = mbase + mt * 16 + (qa & 1) * 8 + rlm;
        int col = (qa >> 1) * 16;
        aAhi[mt] = (uint32_t)__cvta_generic_to_shared(sAhi) + row * ROWB + col;
        aAlo[mt] = (uint32_t)__cvta_generic_to_shared(sAlo) + row * ROWB + col;
    }
    const int lb = lane & 15;
    uint32_t aBhi[NT], aBlo[NT];
#pragma unroll
    for (int nt = 0; nt < NT; nt++) {
        int row = nbase + nt * 8 + (lb & 7);
        int col = ((lb >> 3) & 1) * 16;
        aBhi[nt] = (uint32_t)__cvta_generic_to_shared(sBhi) + row * ROWB + col;
        aBlo[nt] = (uint32_t)__cvta_generic_to_shared(sBlo) + row * ROWB + col;
    }

    const int ntiles = (nrows + 63) / 64;
    for (int t = blockIdx.x; t < ntiles; t += gridDim.x) {
        const int r0 = t * 64;
        __syncthreads();

        // stage A tile: straight uint4 copies of both planes (64 rows x 16 chunks x 2)
#pragma unroll
        for (int it = 0; it < 8; it++) {
            int i = tid + it * 256;
            int plane = i >> 10;            // 0: hi, 1: lo
            int m = (i & 1023) >> 4;
            int q = i & 15;
            int gr = r0 + m;
            uint4 v = make_uint4(0u, 0u, 0u, 0u);
            if (gr < nrows)
                v = reinterpret_cast<const uint4*>((plane ? Alo : Ahi) + (size_t)gr * 128)[q];
            *reinterpret_cast<uint4*>((plane ? sAlo : sAhi) + m * ROWB + q * 16) = v;
        }
        __syncthreads();

        float acc[2][NT][4];
#pragma unroll
        for (int mt = 0; mt < 2; mt++)
#pragma unroll
            for (int nt = 0; nt < NT; nt++)
#pragma unroll
                for (int j = 0; j < 4; j++) acc[mt][nt][j] = 0.0f;

#pragma unroll
        for (int ks = 0; ks < 8; ks++) {
            const uint32_t ko = ks * 32;
            uint32_t ah[2][4], al[2][4];
#pragma unroll
            for (int mt = 0; mt < 2; mt++) {
                LDMX4(ah[mt][0], ah[mt][1], ah[mt][2], ah[mt][3], aAhi[mt] + ko);
                LDMX4(al[mt][0], al[mt][1], al[mt][2], al[mt][3], aAlo[mt] + ko);
            }
#pragma unroll
            for (int nt = 0; nt < NT; nt++) {
                uint32_t bh0, bh1, bl0, bl1;
                LDMX2(bh0, bh1, aBhi[nt] + ko);
                LDMX2(bl0, bl1, aBlo[nt] + ko);
#pragma unroll
                for (int mt = 0; mt < 2; mt++) {
                    MMA_BF16(acc[mt][nt], ah[mt], bh0, bh1);
                    MMA_BF16(acc[mt][nt], ah[mt], bl0, bl1);
                    MMA_BF16(acc[mt][nt], al[mt], bh0, bh1);
                }
            }
        }

#pragma unroll
        for (int mt = 0; mt < 2; mt++) {
#pragma unroll
            for (int nt = 0; nt < NT; nt++) {
                int r1 = r0 + mbase + mt * 16 + g;
                int r2 = r1 + 8;
                int cc = nbase + nt * 8 + tg * 2;
                if (r1 < nrows)
                    *reinterpret_cast<__half2*>(C + (size_t)r1 * NCOL + cc) =
                        __floats2half2_rn(acc[mt][nt][0], acc[mt][nt][1]);
                if (r2 < nrows)
                    *reinterpret_cast<__half2*>(C + (size_t)r2 * NCOL + cc) =
                        __floats2half2_rn(acc[mt][nt][2], acc[mt][nt][3]);
            }
        }
    }
}

// ---------------- agg1: mean + relu, fp16 in -> bf16 hi/lo out ---------------
__global__ void k_agg1(const __half* __restrict__ src,
                       __nv_bfloat16* __restrict__ dhi, __nv_bfloat16* __restrict__ dlo) {
    const int gw = (blockIdx.x * blockDim.x + threadIdx.x) >> 5;
    if (gw >= NN) return;
    const int lane = threadIdx.x & 31;

    const int d = g_deg[gw];
    const int cnt = d < CAP ? d : CAP;
    const int* __restrict__ adj = g_adj + (size_t)gw * CAP;

    float acc[4] = {0.f, 0.f, 0.f, 0.f};
#pragma unroll 4
    for (int t = 0; t < cnt; t++) {
        int j = __ldg(&adj[t]);
        uint2 v = *reinterpret_cast<const uint2*>(src + (size_t)j * 128 + lane * 4);
        float2 f0 = __half22float2(*reinterpret_cast<__half2*>(&v.x));
        float2 f1 = __half22float2(*reinterpret_cast<__half2*>(&v.y));
        acc[0] += f0.x; acc[1] += f0.y; acc[2] += f1.x; acc[3] += f1.y;
    }

    const float inv = 1.0f / (float)d;
    float o0 = fmaxf(acc[0] * inv, 0.f), o1 = fmaxf(acc[1] * inv, 0.f);
    float o2 = fmaxf(acc[2] * inv, 0.f), o3 = fmaxf(acc[3] * inv, 0.f);

    __nv_bfloat162 h01 = __float22bfloat162_rn(make_float2(o0, o1));
    __nv_bfloat162 h23 = __float22bfloat162_rn(make_float2(o2, o3));
    float2 f01 = __bfloat1622float2(h01);
    float2 f23 = __bfloat1622float2(h23);
    __nv_bfloat162 l01 = __float22bfloat162_rn(make_float2(o0 - f01.x, o1 - f01.y));
    __nv_bfloat162 l23 = __float22bfloat162_rn(make_float2(o2 - f23.x, o3 - f23.y));

    size_t off = (size_t)gw * 128 + lane * 4;
    *reinterpret_cast<uint2*>(dhi + off) = make_uint2(
        *reinterpret_cast<uint32_t*>(&h01), *reinterpret_cast<uint32_t*>(&h23));
    *reinterpret_cast<uint2*>(dlo + off) = make_uint2(
        *reinterpret_cast<uint32_t*>(&l01), *reinterpret_cast<uint32_t*>(&l23));
}

// ---------------- agg2: mean, fp16 in -> fp32 out -----------------------------
__global__ void k_agg2(const __half* __restrict__ src, float* __restrict__ dst) {
    const int gw = (blockIdx.x * blockDim.x + threadIdx.x) >> 5;
    if (gw >= NN) return;
    const int lane = threadIdx.x & 31;

    const int d = g_deg[gw];
    const int cnt = d < CAP ? d : CAP;
    const int* __restrict__ adj = g_adj + (size_t)gw * CAP;

    float acc0 = 0.f, acc1 = 0.f;
#pragma unroll 4
    for (int t = 0; t < cnt; t++) {
        int j = __ldg(&adj[t]);
        uint32_t v = *reinterpret_cast<const uint32_t*>(src + (size_t)j * 64 + lane * 2);
        float2 f = __half22float2(*reinterpret_cast<__half2*>(&v));
        acc0 += f.x; acc1 += f.y;
    }
    const float inv = 1.0f / (float)d;
    *reinterpret_cast<float2*>(dst + (size_t)gw * 64 + lane * 2) =
        make_float2(acc0 * inv, acc1 * inv);
}

// ---------------- launch --------------------------------------------------------
extern "C" void kernel_launch(void* const* d_in, const int* in_sizes, int n_in,
                              void* d_out, int out_size) {
    const float* x    = (const float*)d_in[0];
    const float* W1   = (const float*)d_in[1];
    const float* W2   = (const float*)d_in[2];
    const int*   erow = (const int*)d_in[3];
    const int*   ecol = (const int*)d_in[4];
    float* out = (float*)d_out;

    __half *h0, *h2;
    __nv_bfloat16 *h1hi, *h1lo, *w1hi, *w1lo, *w2hi, *w2lo;
    cudaGetSymbolAddress((void**)&h0,   g_h0);
    cudaGetSymbolAddress((void**)&h1hi, g_h1hi);
    cudaGetSymbolAddress((void**)&h1lo, g_h1lo);
    cudaGetSymbolAddress((void**)&h2,   g_h2);
    cudaGetSymbolAddress((void**)&w1hi, g_w1hi);
    cudaGetSymbolAddress((void**)&w1lo, g_w1lo);
    cudaGetSymbolAddress((void**)&w2hi, g_w2hi);
    cudaGetSymbolAddress((void**)&w2lo, g_w2lo);

    const int SMEM1 = 2 * 128 * ROWB + 2 * 64 * ROWB;  // 104448 -> 2 CTA/SM
    const int SMEM2 = 2 * 64 * ROWB + 2 * 64 * ROWB;   //  69632 -> 3 CTA/SM
    cudaFuncSetAttribute(k_gemm_conv, cudaFuncAttributeMaxDynamicSharedMemorySize, SMEM1);
    cudaFuncSetAttribute(k_gemm_pre,  cudaFuncAttributeMaxDynamicSharedMemorySize, SMEM2);

    // launch order puts gemm1 in profiler slot #4
    k_prep_w1<<<(NN + 255) / 256, 256>>>(W1, w1hi, w1lo);                         // 1
    k_prep_w2<<<(128 * 64 + 255) / 256, 256>>>(W2, w2hi, w2lo);                   // 2
    k_build_adj<<<(EE / 4 + 255) / 256, 256>>>(erow, ecol);                       // 3
    k_gemm_conv<<<2 * NSM, 256, SMEM1>>>(x, w1hi, w1lo, h0, NN);                  // 4
    k_agg1<<<(NN * 32 + 255) / 256, 256>>>(h0, h1hi, h1lo);                       // 5
    k_gemm_pre<<<3 * NSM, 256, SMEM2>>>(h1hi, h1lo, w2hi, w2lo, h2, NN);          // 6
    k_agg2<<<(NN * 32 + 255) / 256, 256>>>(h2, out);                              // 7
}